// round 16
// baseline (speedup 1.0000x reference)
#include <cuda_runtime.h>
#include <cstdint>

#define NN 4096
#define DD 128
#define EPSF 1e-12f
#define KS 8            // split-K factor for GEMMs (256 CTAs -> 2/SM)
#define BM 128          // GEMM block rows
#define BK 16           // GEMM k-tile
#define AS_STRIDE 20    // floats; conflict-free for As[m][k] frag reads
#define BS_STRIDE 136   // floats; conflict-free for Bs[k][n] frag reads

// Scratch (static device allocation — no cudaMalloc allowed).
// RULE: __device__ symbols are NEVER passed as kernel args from host code.
__device__ __align__(256) float g_att[(size_t)NN * NN];  // 64 MB dense att input
__device__ __align__(256) float g_feat[NN * DD];         // W @ activities (raw fp32)
__device__ __align__(256) float g_Bcvt[NN * DD];         // current B, tf32-rounded
__device__ __align__(256) float g_norm[NN];              // row sums of g_att
__device__ int g_is64;                                   // index dtype sniff

// ---------------------------------------------------------------------------
// Kernel 0: zero HALF of att (+ norm & dtype sniff when half==0).
// Split across the two streams so ~7us of the zeroing leaves the critical path.
// ---------------------------------------------------------------------------
__global__ void k_zero(const unsigned* __restrict__ cur_raw, int half) {
    if (half == 0 && blockIdx.x == 0 && threadIdx.x == 0) {
        unsigned o = 0;
#pragma unroll
        for (int i = 1; i < 128; i += 2) o |= cur_raw[i];
        g_is64 = (o == 0) ? 1 : 0;
    }
    size_t idx    = (size_t)blockIdx.x * blockDim.x + threadIdx.x;
    size_t stride = (size_t)gridDim.x * blockDim.x;
    float4 z = make_float4(0.f, 0.f, 0.f, 0.f);
    const size_t na2 = ((size_t)NN * NN) / 8;       // half, in float4s
    float4* pa = (float4*)g_att + (size_t)half * na2;
    for (size_t i = idx; i < na2; i += stride) pa[i] = z;
    if (half == 0)
        for (size_t i = idx; i < NN; i += stride) g_norm[i] = 0.f;
}

// ---------------------------------------------------------------------------
// Kernel 1: 4 edges per warp, 8 lanes per edge, 4 float4-chunks per lane.
// __launch_bounds__(256,3): ~85-reg budget so ptxas keeps all 12 LDG.128
// outstanding (R15 shipped regs=32 => loads were serialized in batches).
// dist = ||h + case - t||, val = exp(-dist); scatter att[t][c], norm[t].
// ---------------------------------------------------------------------------
__global__ void __launch_bounds__(256, 3)
k_edge(const void* __restrict__ curp, const void* __restrict__ tgtp,
       const float* __restrict__ act, const float* __restrict__ cases,
       int E) {
    int wid  = (int)((blockIdx.x * blockDim.x + threadIdx.x) >> 5);
    int lane = threadIdx.x & 31;
    int g    = lane >> 3;      // edge slot within warp (0..3)
    int sub  = lane & 7;       // lane within edge group
    int e    = wid * 4 + g;
    if (e >= E) return;

    int c, t;
    if (g_is64) {
        c = (int)((const long long*)curp)[e];
        t = (int)((const long long*)tgtp)[e];
    } else {
        c = ((const int*)curp)[e];
        t = ((const int*)tgtp)[e];
    }

    const float4* ha = (const float4*)act   + (size_t)c * (DD / 4) + sub;
    const float4* ta = (const float4*)act   + (size_t)t * (DD / 4) + sub;
    const float4* ca = (const float4*)cases + (size_t)e * (DD / 4) + sub;

    float4 hv[4], tv[4], cv[4];
#pragma unroll
    for (int i = 0; i < 4; i++) {           // 12 LDG.128 issued back-to-back
        hv[i] = ha[i * 8];
        tv[i] = ta[i * 8];
        cv[i] = __ldcs(ca + i * 8);
    }

    float s = 0.f;
#pragma unroll
    for (int i = 0; i < 4; i++) {
        float dx = hv[i].x + cv[i].x - tv[i].x;
        float dy = hv[i].y + cv[i].y - tv[i].y;
        float dz = hv[i].z + cv[i].z - tv[i].z;
        float dw = hv[i].w + cv[i].w - tv[i].w;
        s = fmaf(dx, dx, s);
        s = fmaf(dy, dy, s);
        s = fmaf(dz, dz, s);
        s = fmaf(dw, dw, s);
    }
    // butterfly within the 8-lane group (covers all 4 edges simultaneously)
    s += __shfl_xor_sync(0xffffffffu, s, 1);
    s += __shfl_xor_sync(0xffffffffu, s, 2);
    s += __shfl_xor_sync(0xffffffffu, s, 4);

    float v = __expf(-sqrtf(s));
    if (sub == 0) atomicAdd(&g_att[(size_t)t * NN + c], v);
    if (sub == 1) atomicAdd(&g_norm[t], v);
}

// ---------------------------------------------------------------------------
// tf32 helpers
// ---------------------------------------------------------------------------
__device__ __forceinline__ unsigned f2tf(float x) {
    unsigned r;
    asm("cvt.rna.tf32.f32 %0, %1;" : "=r"(r) : "f"(x));
    return r;
}

// ---------------------------------------------------------------------------
// Kernel 2: elementwise tf32-round source -> g_Bcvt (SAME layout).
// Source selected DEVICE-SIDE: use_feat ? g_feat : Xin. Optional extras:
//   outc != null  -> write source verbatim to outc ("out = feat" pre-init)
//   zero_feat     -> also zero g_feat (pre-init for GEMM1's atomic epilogue)
// ---------------------------------------------------------------------------
__global__ void k_prepB(const float* __restrict__ Xin, int use_feat,
                        float* __restrict__ outc, int zero_feat) {
    const float* X = use_feat ? g_feat : Xin;
    int idx = blockIdx.x * blockDim.x + threadIdx.x;   // 0 .. 131071
    float4 v = ((const float4*)X)[idx];
    float4 r;
    r.x = __uint_as_float(f2tf(v.x));
    r.y = __uint_as_float(f2tf(v.y));
    r.z = __uint_as_float(f2tf(v.z));
    r.w = __uint_as_float(f2tf(v.w));
    ((float4*)g_Bcvt)[idx] = r;
    if (outc) ((float4*)outc)[idx] = v;
    if (zero_feat) ((float4*)g_feat)[idx] = make_float4(0.f, 0.f, 0.f, 0.f);
}

__device__ __forceinline__ void mma8(float* c, unsigned a0, unsigned a1,
                                     unsigned a2, unsigned a3,
                                     unsigned b0, unsigned b1) {
    asm volatile(
        "mma.sync.aligned.m16n8k8.row.col.f32.tf32.tf32.f32 "
        "{%0,%1,%2,%3}, {%4,%5,%6,%7}, {%8,%9}, {%0,%1,%2,%3};"
        : "+f"(c[0]), "+f"(c[1]), "+f"(c[2]), "+f"(c[3])
        : "r"(a0), "r"(a1), "r"(a2), "r"(a3), "r"(b0), "r"(b1));
}

__device__ __forceinline__ void cp16(float* smem_dst, const float* gmem_src) {
    unsigned sa = (unsigned)__cvta_generic_to_shared(smem_dst);
    asm volatile("cp.async.cg.shared.global [%0], [%1], 16;" :: "r"(sa), "l"(gmem_src));
}

// ---------------------------------------------------------------------------
// Kernel 4: tensor-core GEMM — proven R12/R14/R15 version (42us/launch).
// B pre-rounded tf32 (g_Bcvt); A fragments cvt.rna in-loop. Double-buffered
// cp.async BK=16 tiles, split-K=8 atomic epilogue, 2 CTAs/SM.
//   mode 0: A=W,     B=g_Bcvt(=tf32(act)),  C=g_feat (zeroed)
//   mode 1: A=g_att, B=g_Bcvt(=tf32(feat)), C=out (holds feat), 1/(norm+eps)
// ---------------------------------------------------------------------------
__global__ void __launch_bounds__(256, 2)
k_gemm_tc(const float* __restrict__ Wp, float* __restrict__ outp, int mode) {
    __shared__ __align__(16) float As[2][BM * AS_STRIDE];  // 20480 B
    __shared__ __align__(16) float Bs[2][BK * BS_STRIDE];  // 17408 B

    const float* A = mode ? g_att : Wp;
    const float* B = g_Bcvt;
    float* C       = mode ? outp  : g_feat;

    const int tid  = threadIdx.x;
    const int lane = tid & 31;
    const int w    = tid >> 5;
    const int wm   = w & 3;      // warp row group (0..3) -> rows wm*32..+32
    const int wn   = w >> 2;     // warp col group (0..1) -> cols wn*64..+64
    const int m0   = blockIdx.x * BM;
    const int k0   = blockIdx.y * (NN / KS);
    const int NT   = (NN / KS) / BK;  // 32 k-tiles

    float acc[2][8][4];
#pragma unroll
    for (int t = 0; t < 2; t++)
#pragma unroll
        for (int j = 0; j < 8; j++)
#pragma unroll
            for (int q = 0; q < 4; q++) acc[t][j][q] = 0.f;

    // ---- tile loader (cp.async, 4 x 16B per thread) ----
    auto load_tile = [&](int buf, int kt) {
#pragma unroll
        for (int s = 0; s < 2; s++) {
            int chunk = tid + 256 * s;              // 0..511
            int row = chunk >> 2, kq = chunk & 3;   // A: 128 rows x 4 float4
            cp16(&As[buf][row * AS_STRIDE + kq * 4],
                 A + (size_t)(m0 + row) * NN + kt + kq * 4);
        }
#pragma unroll
        for (int s = 0; s < 2; s++) {
            int chunk = tid + 256 * s;
            int kr = chunk >> 5, nq = chunk & 31;   // B: 16 rows x 32 float4
            cp16(&Bs[buf][kr * BS_STRIDE + nq * 4],
                 B + (size_t)(kt + kr) * DD + nq * 4);
        }
        asm volatile("cp.async.commit_group;");
    };

    load_tile(0, k0);

    for (int it = 0; it < NT; it++) {
        int buf = it & 1;
        if (it + 1 < NT) {
            load_tile(buf ^ 1, k0 + (it + 1) * BK);
            asm volatile("cp.async.wait_group 1;");
        } else {
            asm volatile("cp.async.wait_group 0;");
        }
        __syncthreads();

#pragma unroll
        for (int ks = 0; ks < BK; ks += 8) {
            // A fragments (m16k8), tf32-converted (rna)
            unsigned ah[2][4];
#pragma unroll
            for (int t = 0; t < 2; t++) {
                int r = wm * 32 + t * 16 + (lane >> 2);
                int c = ks + (lane & 3);
                ah[t][0] = f2tf(As[buf][r * AS_STRIDE + c]);
                ah[t][1] = f2tf(As[buf][(r + 8) * AS_STRIDE + c]);
                ah[t][2] = f2tf(As[buf][r * AS_STRIDE + c + 4]);
                ah[t][3] = f2tf(As[buf][(r + 8) * AS_STRIDE + c + 4]);
            }
#pragma unroll
            for (int jb = 0; jb < 2; jb++) {
                unsigned bh[4][2];
#pragma unroll
                for (int jj = 0; jj < 4; jj++) {
                    int j = jb * 4 + jj;
                    int kk = ks + (lane & 3);
                    int n  = wn * 64 + j * 8 + (lane >> 2);
                    bh[jj][0] = __float_as_uint(Bs[buf][kk * BS_STRIDE + n]);
                    bh[jj][1] = __float_as_uint(Bs[buf][(kk + 4) * BS_STRIDE + n]);
                }
#pragma unroll
                for (int t = 0; t < 2; t++)
#pragma unroll
                    for (int jj = 0; jj < 4; jj++) {
                        mma8(acc[t][jb * 4 + jj], ah[t][0], ah[t][1], ah[t][2],
                             ah[t][3], bh[jj][0], bh[jj][1]);
                    }
            }
        }
        __syncthreads();
    }

    // ---- epilogue: split-K atomic accumulate (mode1 scales by 1/(norm+eps)) ----
#pragma unroll
    for (int t = 0; t < 2; t++) {
        int r0 = m0 + wm * 32 + t * 16 + (lane >> 2);
        float inv0 = 1.f, inv1 = 1.f;
        if (mode) {
            inv0 = 1.f / (g_norm[r0] + EPSF);
            inv1 = 1.f / (g_norm[r0 + 8] + EPSF);
        }
#pragma unroll
        for (int j = 0; j < 8; j++) {
            int cc = wn * 64 + j * 8 + (lane & 3) * 2;
            atomicAdd(&C[(size_t)r0 * DD + cc],           inv0 * acc[t][j][0]);
            atomicAdd(&C[(size_t)r0 * DD + cc + 1],       inv0 * acc[t][j][1]);
            atomicAdd(&C[(size_t)(r0 + 8) * DD + cc],     inv1 * acc[t][j][2]);
            atomicAdd(&C[(size_t)(r0 + 8) * DD + cc + 1], inv1 * acc[t][j][3]);
        }
    }
}

// ---------------------------------------------------------------------------
// Launch graph:
//   stream B: zero(att half1) ─ evZB ─ prepB(act)+zero feat ─ GEMM1 ─
//             prepB(feat)+out=feat ─ evJoin
//   stream A: zero(att half0) ──────── wait(evZB) ─ edge ─ wait(evJoin) ─ GEMM2
// Edge overlaps GEMM1 AND the feat-prep; post-join work is GEMM2 only.
// ---------------------------------------------------------------------------
extern "C" void kernel_launch(void* const* d_in, const int* in_sizes, int n_in,
                              void* d_out, int out_size) {
    const void*  cur   = d_in[0];                 // currents (int64 or int32), [E]
    const void*  tgt   = d_in[1];                 // targets, [E]
    const float* act   = (const float*)d_in[2];   // activities_features [N, D]
    const float* cases = (const float*)d_in[3];   // cases_features [E, D]
    const float* W     = (const float*)d_in[4];   // W [N, N]
    float* out = (float*)d_out;                   // h [N, D]

    int E = in_sizes[3] / DD;                     // unambiguous regardless of index dtype

    static cudaStream_t s2 = nullptr;
    static cudaEvent_t evFork = nullptr, evZB = nullptr, evJoin = nullptr;
    if (!s2) {
        cudaStreamCreateWithFlags(&s2, cudaStreamNonBlocking);
        cudaEventCreateWithFlags(&evFork, cudaEventDisableTiming);
        cudaEventCreateWithFlags(&evZB, cudaEventDisableTiming);
        cudaEventCreateWithFlags(&evJoin, cudaEventDisableTiming);
    }

    // ---- fork ----
    cudaEventRecord(evFork, 0);
    cudaStreamWaitEvent(s2, evFork, 0);

    // Branch B: zero att upper half, then prepB(act)+zero feat, GEMM1,
    // then prepB(feat)+out=feat (overlaps the edge tail on stream A).
    k_zero<<<2048, 256, 0, s2>>>((const unsigned*)cur, 1);
    cudaEventRecord(evZB, s2);
    k_prepB<<<512, 256, 0, s2>>>(act, 0, nullptr, 1);
    k_gemm_tc<<<dim3(NN / BM, KS), 256, 0, s2>>>(W, nullptr, 0);
    k_prepB<<<512, 256, 0, s2>>>(nullptr, 1, out, 0);
    cudaEventRecord(evJoin, s2);

    // Branch A: zero att lower half (+ norm + sniff), wait for B's half, edge.
    k_zero<<<2048, 256>>>((const unsigned*)cur, 0);
    cudaStreamWaitEvent(0, evZB, 0);
    k_edge<<<(E / 4 + 7) / 8, 256>>>(cur, tgt, act, cases, E);

    // ---- join; GEMM2 is the only post-join work ----
    cudaStreamWaitEvent(0, evJoin, 0);
    k_gemm_tc<<<dim3(NN / BM, KS), 256>>>(W, out, 1);
}

// round 17
// speedup vs baseline: 1.0613x; 1.0613x over previous
#include <cuda_runtime.h>
#include <cstdint>

#define NN 4096
#define DD 128
#define EPSF 1e-12f
#define KS 8            // split-K factor for GEMMs (256 CTAs -> 2/SM)
#define BM 128          // GEMM block rows
#define BK 16           // GEMM k-tile
#define AS_STRIDE 20    // floats; conflict-free for As[m][k] frag reads
#define BS_STRIDE 136   // floats; conflict-free for Bs[k][n] frag reads

// Scratch (static device allocation — no cudaMalloc allowed).
// RULE: __device__ symbols are NEVER passed as kernel args from host code.
__device__ __align__(256) float g_att[(size_t)NN * NN];  // 64 MB dense att input
__device__ __align__(256) float g_feat[NN * DD];         // W @ activities (raw fp32)
__device__ __align__(256) float g_Bcvt[NN * DD];         // current B, tf32-rounded
__device__ __align__(256) float g_norm[NN];              // row sums of g_att
__device__ int g_is64;                                   // index dtype sniff

// ---------------------------------------------------------------------------
// Kernel 0: zero att + norm, sniff int64 vs int32 indices. (R15-exact)
// ---------------------------------------------------------------------------
__global__ void k_zero(const unsigned* __restrict__ cur_raw) {
    if (blockIdx.x == 0 && threadIdx.x == 0) {
        unsigned o = 0;
#pragma unroll
        for (int i = 1; i < 128; i += 2) o |= cur_raw[i];
        g_is64 = (o == 0) ? 1 : 0;
    }
    size_t idx    = (size_t)blockIdx.x * blockDim.x + threadIdx.x;
    size_t stride = (size_t)gridDim.x * blockDim.x;
    float4 z = make_float4(0.f, 0.f, 0.f, 0.f);
    float4* pa = (float4*)g_att;
    const size_t na = ((size_t)NN * NN) / 4;
    for (size_t i = idx; i < na; i += stride) pa[i] = z;
    for (size_t i = idx; i < NN; i += stride) g_norm[i] = 0.f;
}

// ---------------------------------------------------------------------------
// Kernel 1: 4 edges per warp, 8 lanes per edge, 4 float4-chunks per lane.
// R15-EXACT (no launch_bounds — the R16 reg-budget experiment regressed it).
// dist = ||h + case - t||, val = exp(-dist); scatter att[t][c], norm[t].
// ---------------------------------------------------------------------------
__global__ void k_edge(const void* __restrict__ curp, const void* __restrict__ tgtp,
                       const float* __restrict__ act, const float* __restrict__ cases,
                       int E) {
    int wid  = (int)((blockIdx.x * blockDim.x + threadIdx.x) >> 5);
    int lane = threadIdx.x & 31;
    int g    = lane >> 3;      // edge slot within warp (0..3)
    int sub  = lane & 7;       // lane within edge group
    int e    = wid * 4 + g;
    if (e >= E) return;

    int c, t;
    if (g_is64) {
        c = (int)((const long long*)curp)[e];
        t = (int)((const long long*)tgtp)[e];
    } else {
        c = ((const int*)curp)[e];
        t = ((const int*)tgtp)[e];
    }

    const float4* ha = (const float4*)act   + (size_t)c * (DD / 4) + sub;
    const float4* ta = (const float4*)act   + (size_t)t * (DD / 4) + sub;
    const float4* ca = (const float4*)cases + (size_t)e * (DD / 4) + sub;

    float4 hv[4], tv[4], cv[4];
#pragma unroll
    for (int i = 0; i < 4; i++) {           // 12 LDG.128 issued back-to-back
        hv[i] = ha[i * 8];
        tv[i] = ta[i * 8];
        cv[i] = __ldcs(ca + i * 8);
    }

    float s = 0.f;
#pragma unroll
    for (int i = 0; i < 4; i++) {
        float dx = hv[i].x + cv[i].x - tv[i].x;
        float dy = hv[i].y + cv[i].y - tv[i].y;
        float dz = hv[i].z + cv[i].z - tv[i].z;
        float dw = hv[i].w + cv[i].w - tv[i].w;
        s = fmaf(dx, dx, s);
        s = fmaf(dy, dy, s);
        s = fmaf(dz, dz, s);
        s = fmaf(dw, dw, s);
    }
    // butterfly within the 8-lane group (covers all 4 edges simultaneously)
    s += __shfl_xor_sync(0xffffffffu, s, 1);
    s += __shfl_xor_sync(0xffffffffu, s, 2);
    s += __shfl_xor_sync(0xffffffffu, s, 4);

    float v = __expf(-sqrtf(s));
    if (sub == 0) atomicAdd(&g_att[(size_t)t * NN + c], v);
    if (sub == 1) atomicAdd(&g_norm[t], v);
}

// ---------------------------------------------------------------------------
// tf32 helpers
// ---------------------------------------------------------------------------
__device__ __forceinline__ unsigned f2tf(float x) {
    unsigned r;
    asm("cvt.rna.tf32.f32 %0, %1;" : "=r"(r) : "f"(x));
    return r;
}

// ---------------------------------------------------------------------------
// Kernel 2: elementwise tf32-round source -> g_Bcvt (SAME layout).
// Source selected DEVICE-SIDE: use_feat ? g_feat : Xin. Optional extras:
//   outc != null  -> write source verbatim to outc ("out = feat" pre-init)
//   zero_feat     -> also zero g_feat (pre-init for GEMM1's atomic epilogue)
// ---------------------------------------------------------------------------
__global__ void k_prepB(const float* __restrict__ Xin, int use_feat,
                        float* __restrict__ outc, int zero_feat) {
    const float* X = use_feat ? g_feat : Xin;
    int idx = blockIdx.x * blockDim.x + threadIdx.x;   // 0 .. 131071
    float4 v = ((const float4*)X)[idx];
    float4 r;
    r.x = __uint_as_float(f2tf(v.x));
    r.y = __uint_as_float(f2tf(v.y));
    r.z = __uint_as_float(f2tf(v.z));
    r.w = __uint_as_float(f2tf(v.w));
    ((float4*)g_Bcvt)[idx] = r;
    if (outc) ((float4*)outc)[idx] = v;
    if (zero_feat) ((float4*)g_feat)[idx] = make_float4(0.f, 0.f, 0.f, 0.f);
}

__device__ __forceinline__ void mma8(float* c, unsigned a0, unsigned a1,
                                     unsigned a2, unsigned a3,
                                     unsigned b0, unsigned b1) {
    asm volatile(
        "mma.sync.aligned.m16n8k8.row.col.f32.tf32.tf32.f32 "
        "{%0,%1,%2,%3}, {%4,%5,%6,%7}, {%8,%9}, {%0,%1,%2,%3};"
        : "+f"(c[0]), "+f"(c[1]), "+f"(c[2]), "+f"(c[3])
        : "r"(a0), "r"(a1), "r"(a2), "r"(a3), "r"(b0), "r"(b1));
}

__device__ __forceinline__ void cp16(float* smem_dst, const float* gmem_src) {
    unsigned sa = (unsigned)__cvta_generic_to_shared(smem_dst);
    asm volatile("cp.async.cg.shared.global [%0], [%1], 16;" :: "r"(sa), "l"(gmem_src));
}

// ---------------------------------------------------------------------------
// Kernel 4: tensor-core GEMM — R15 base + A-fragment preload for BOTH k-steps
// right after the tile barrier (16 LDS issued back-to-back so k-step 1's LDS
// latency hides under k-step 0's MMAs). +8 regs, still under the 128 cap.
//   mode 0: A=W,     B=g_Bcvt(=tf32(act)),  C=g_feat (zeroed)
//   mode 1: A=g_att, B=g_Bcvt(=tf32(feat)), C=out (holds feat), 1/(norm+eps)
// ---------------------------------------------------------------------------
__global__ void __launch_bounds__(256, 2)
k_gemm_tc(const float* __restrict__ Wp, float* __restrict__ outp, int mode) {
    __shared__ __align__(16) float As[2][BM * AS_STRIDE];  // 20480 B
    __shared__ __align__(16) float Bs[2][BK * BS_STRIDE];  // 17408 B

    const float* A = mode ? g_att : Wp;
    const float* B = g_Bcvt;
    float* C       = mode ? outp  : g_feat;

    const int tid  = threadIdx.x;
    const int lane = tid & 31;
    const int w    = tid >> 5;
    const int wm   = w & 3;      // warp row group (0..3) -> rows wm*32..+32
    const int wn   = w >> 2;     // warp col group (0..1) -> cols wn*64..+64
    const int m0   = blockIdx.x * BM;
    const int k0   = blockIdx.y * (NN / KS);
    const int NT   = (NN / KS) / BK;  // 32 k-tiles

    float acc[2][8][4];
#pragma unroll
    for (int t = 0; t < 2; t++)
#pragma unroll
        for (int j = 0; j < 8; j++)
#pragma unroll
            for (int q = 0; q < 4; q++) acc[t][j][q] = 0.f;

    // ---- tile loader (cp.async, 4 x 16B per thread) ----
    auto load_tile = [&](int buf, int kt) {
#pragma unroll
        for (int s = 0; s < 2; s++) {
            int chunk = tid + 256 * s;              // 0..511
            int row = chunk >> 2, kq = chunk & 3;   // A: 128 rows x 4 float4
            cp16(&As[buf][row * AS_STRIDE + kq * 4],
                 A + (size_t)(m0 + row) * NN + kt + kq * 4);
        }
#pragma unroll
        for (int s = 0; s < 2; s++) {
            int chunk = tid + 256 * s;
            int kr = chunk >> 5, nq = chunk & 31;   // B: 16 rows x 32 float4
            cp16(&Bs[buf][kr * BS_STRIDE + nq * 4],
                 B + (size_t)(kt + kr) * DD + nq * 4);
        }
        asm volatile("cp.async.commit_group;");
    };

    load_tile(0, k0);

    for (int it = 0; it < NT; it++) {
        int buf = it & 1;
        if (it + 1 < NT) {
            load_tile(buf ^ 1, k0 + (it + 1) * BK);
            asm volatile("cp.async.wait_group 1;");
        } else {
            asm volatile("cp.async.wait_group 0;");
        }
        __syncthreads();

        // ---- preload A fragments for BOTH k-steps (16 LDS back-to-back) ----
        unsigned ah[2][2][4];   // [kstep][t][reg]
#pragma unroll
        for (int kstep = 0; kstep < 2; kstep++)
#pragma unroll
            for (int t = 0; t < 2; t++) {
                int r = wm * 32 + t * 16 + (lane >> 2);
                int c = kstep * 8 + (lane & 3);
                ah[kstep][t][0] = f2tf(As[buf][r * AS_STRIDE + c]);
                ah[kstep][t][1] = f2tf(As[buf][(r + 8) * AS_STRIDE + c]);
                ah[kstep][t][2] = f2tf(As[buf][r * AS_STRIDE + c + 4]);
                ah[kstep][t][3] = f2tf(As[buf][(r + 8) * AS_STRIDE + c + 4]);
            }

#pragma unroll
        for (int kstep = 0; kstep < 2; kstep++) {
            int ks = kstep * 8;
#pragma unroll
            for (int jb = 0; jb < 2; jb++) {
                unsigned bh[4][2];
#pragma unroll
                for (int jj = 0; jj < 4; jj++) {
                    int j = jb * 4 + jj;
                    int kk = ks + (lane & 3);
                    int n  = wn * 64 + j * 8 + (lane >> 2);
                    bh[jj][0] = __float_as_uint(Bs[buf][kk * BS_STRIDE + n]);
                    bh[jj][1] = __float_as_uint(Bs[buf][(kk + 4) * BS_STRIDE + n]);
                }
#pragma unroll
                for (int t = 0; t < 2; t++)
#pragma unroll
                    for (int jj = 0; jj < 4; jj++) {
                        mma8(acc[t][jb * 4 + jj],
                             ah[kstep][t][0], ah[kstep][t][1],
                             ah[kstep][t][2], ah[kstep][t][3],
                             bh[jj][0], bh[jj][1]);
                    }
            }
        }
        __syncthreads();
    }

    // ---- epilogue: split-K atomic accumulate (mode1 scales by 1/(norm+eps)) ----
#pragma unroll
    for (int t = 0; t < 2; t++) {
        int r0 = m0 + wm * 32 + t * 16 + (lane >> 2);
        float inv0 = 1.f, inv1 = 1.f;
        if (mode) {
            inv0 = 1.f / (g_norm[r0] + EPSF);
            inv1 = 1.f / (g_norm[r0 + 8] + EPSF);
        }
#pragma unroll
        for (int j = 0; j < 8; j++) {
            int cc = wn * 64 + j * 8 + (lane & 3) * 2;
            atomicAdd(&C[(size_t)r0 * DD + cc],           inv0 * acc[t][j][0]);
            atomicAdd(&C[(size_t)r0 * DD + cc + 1],       inv0 * acc[t][j][1]);
            atomicAdd(&C[(size_t)(r0 + 8) * DD + cc],     inv1 * acc[t][j][2]);
            atomicAdd(&C[(size_t)(r0 + 8) * DD + cc + 1], inv1 * acc[t][j][3]);
        }
    }
}

// ---------------------------------------------------------------------------
// Launch graph (R15 structure; only prepB(feat) lives on stream B now):
//   stream B: prepB(act)+zero feat ─ GEMM1 ─ prepB(feat)+out=feat ─ evJoin
//   stream A: zero(att+norm) ─ edge ─ wait(evJoin) ─ GEMM2
// ---------------------------------------------------------------------------
extern "C" void kernel_launch(void* const* d_in, const int* in_sizes, int n_in,
                              void* d_out, int out_size) {
    const void*  cur   = d_in[0];                 // currents (int64 or int32), [E]
    const void*  tgt   = d_in[1];                 // targets, [E]
    const float* act   = (const float*)d_in[2];   // activities_features [N, D]
    const float* cases = (const float*)d_in[3];   // cases_features [E, D]
    const float* W     = (const float*)d_in[4];   // W [N, N]
    float* out = (float*)d_out;                   // h [N, D]

    int E = in_sizes[3] / DD;                     // unambiguous regardless of index dtype

    static cudaStream_t s2 = nullptr;
    static cudaEvent_t evFork = nullptr, evJoin = nullptr;
    if (!s2) {
        cudaStreamCreateWithFlags(&s2, cudaStreamNonBlocking);
        cudaEventCreateWithFlags(&evFork, cudaEventDisableTiming);
        cudaEventCreateWithFlags(&evJoin, cudaEventDisableTiming);
    }

    // ---- fork ----
    cudaEventRecord(evFork, 0);
    cudaStreamWaitEvent(s2, evFork, 0);

    // Branch B: prepB(act)+zero feat, GEMM1, then prepB(feat)+out=feat
    // (the last overlaps the edge tail on stream A).
    k_prepB<<<512, 256, 0, s2>>>(act, 0, nullptr, 1);
    k_gemm_tc<<<dim3(NN / BM, KS), 256, 0, s2>>>(W, nullptr, 0);
    k_prepB<<<512, 256, 0, s2>>>(nullptr, 1, out, 0);
    cudaEventRecord(evJoin, s2);

    // Branch A: zero att+norm (+sniff), then edge scatter (4 edges/warp).
    k_zero<<<4096, 256>>>((const unsigned*)cur);
    k_edge<<<(E / 4 + 7) / 8, 256>>>(cur, tgt, act, cases, E);

    // ---- join; GEMM2 is the only post-join work ----
    cudaStreamWaitEvent(0, evJoin, 0);
    k_gemm_tc<<<dim3(NN / BM, KS), 256>>>(W, out, 1);
}